// round 7
// baseline (speedup 1.0000x reference)
#include <cuda_runtime.h>
#include <math.h>
#include <stdint.h>

#define T_TOK 1024
#define H_DIM 1024
#define E_NUM 32
#define I_DIM 512
#define IS_DIM 2048
#define NGROUP 8
#define GSIZE 4
#define TOPKG 4
#define TOPK 8
#define RSCALE 2.5f

// Scratch: activations stored as tf32 bit patterns (pre-converted)
__device__ uint32_t g_xtf[(size_t)T_TOK * H_DIM];
__device__ uint32_t g_act[(size_t)E_NUM * T_TOK * I_DIM];
__device__ uint32_t g_sact[(size_t)T_TOK * IS_DIM];
__device__ int   g_cnt[E_NUM];
__device__ int   g_tok[E_NUM * T_TOK];
__device__ float g_wgt[E_NUM * T_TOK];

__device__ __forceinline__ float silu_f(float v) { return v / (1.f + expf(-v)); }

__device__ __forceinline__ uint32_t f2tf(float f) {
    uint32_t u;
    asm("cvt.rna.tf32.f32 %0, %1;" : "=r"(u) : "f"(f));
    return u;
}

__device__ __forceinline__ uint32_t smem_u32(const void* p) {
    uint32_t a;
    asm("{ .reg .u64 t; cvta.to.shared.u64 t, %1; cvt.u32.u64 %0, t; }" : "=r"(a) : "l"(p));
    return a;
}

__device__ __forceinline__ void mma_tf32(float* c,
                                         uint32_t a0, uint32_t a1, uint32_t a2, uint32_t a3,
                                         uint32_t b0, uint32_t b1)
{
    asm volatile(
        "mma.sync.aligned.m16n8k8.row.col.f32.tf32.tf32.f32 "
        "{%0,%1,%2,%3}, {%4,%5,%6,%7}, {%8,%9}, {%0,%1,%2,%3};\n"
        : "+f"(c[0]), "+f"(c[1]), "+f"(c[2]), "+f"(c[3])
        : "r"(a0), "r"(a1), "r"(a2), "r"(a3), "r"(b0), "r"(b1));
}

#define CP16(dst, src, sz) \
    asm volatile("cp.async.cg.shared.global [%0], [%1], 16, %2;" \
                 :: "r"(dst), "l"(src), "r"(sz) : "memory")
#define CP_COMMIT() asm volatile("cp.async.commit_group;" ::: "memory")
#define CP_WAIT2()  asm volatile("cp.async.wait_group 2;" ::: "memory")

// init: zero expert counters + zero output (atomicAdd target)
__global__ void k_init(float* __restrict__ out) {
    if (blockIdx.x == 0 && threadIdx.x < E_NUM) g_cnt[threadIdx.x] = 0;
    size_t i = (size_t)blockIdx.x * 256 + threadIdx.x;
    ((float4*)out)[i] = make_float4(0.f, 0.f, 0.f, 0.f);
}

// convert X -> tf32 bits once
__global__ void k_xtf(const float* __restrict__ x) {
    size_t i = (size_t)blockIdx.x * 256 + threadIdx.x;
    float4 v = ((const float4*)x)[i];
    ((uint4*)g_xtf)[i] = make_uint4(f2tf(v.x), f2tf(v.y), f2tf(v.z), f2tf(v.w));
}

// ---------------------------------------------------------------------------
// Gate GEMV + DeepseekV3 noaux_tc routing + per-expert gather
// ---------------------------------------------------------------------------
__global__ __launch_bounds__(256) void k_gate_route(
    const float* __restrict__ x,
    const float* __restrict__ gate_w,
    const float* __restrict__ e_bias)
{
    __shared__ float s_logit[E_NUM];
    const int t = blockIdx.x;
    const int warp = threadIdx.x >> 5, lane = threadIdx.x & 31;
    const float* xr = x + (size_t)t * H_DIM;
    for (int e = warp; e < E_NUM; e += 8) {
        const float* gw = gate_w + (size_t)e * H_DIM;
        float s = 0.f;
        for (int k = lane; k < H_DIM; k += 32) s += xr[k] * gw[k];
        #pragma unroll
        for (int o = 16; o; o >>= 1) s += __shfl_xor_sync(0xffffffffu, s, o);
        if (lane == 0) s_logit[e] = s;
    }
    __syncthreads();
    if (threadIdx.x != 0) return;

    float scores[E_NUM], swb[E_NUM];
    for (int e = 0; e < E_NUM; e++) {
        float sc = 1.f / (1.f + expf(-s_logit[e]));
        scores[e] = sc;
        swb[e] = sc + e_bias[e];
    }
    float gs[NGROUP];
    for (int g = 0; g < NGROUP; g++) {
        float m1 = -1e30f, m2 = -1e30f;
        for (int j = 0; j < GSIZE; j++) {
            float v = swb[g * GSIZE + j];
            if (v > m1) { m2 = m1; m1 = v; }
            else if (v > m2) m2 = v;
        }
        gs[g] = m1 + m2;
    }
    bool gsel[NGROUP] = {false};
    for (int it = 0; it < TOPKG; it++) {
        int bi = 0; float bv = -1e30f;
        for (int g = 0; g < NGROUP; g++)
            if (!gsel[g] && gs[g] > bv) { bv = gs[g]; bi = g; }
        gsel[bi] = true;
    }
    float val[E_NUM];
    for (int e = 0; e < E_NUM; e++) val[e] = gsel[e / GSIZE] ? swb[e] : 0.f;
    bool taken[E_NUM] = {false};
    int sel[TOPK];
    float denom = 0.f;
    for (int it = 0; it < TOPK; it++) {
        int bi = 0; float bv = -1e30f;
        for (int e = 0; e < E_NUM; e++)
            if (!taken[e] && val[e] > bv) { bv = val[e]; bi = e; }
        taken[bi] = true; sel[it] = bi; denom += scores[bi];
    }
    float inv = RSCALE / (denom + 1e-20f);
    for (int it = 0; it < TOPK; it++) {
        int e = sel[it];
        int slot = atomicAdd(&g_cnt[e], 1);
        g_tok[e * T_TOK + slot] = t;
        g_wgt[e * T_TOK + slot] = scores[e] * inv;
    }
}

// ---------------------------------------------------------------------------
// Shared layout per stage (32-bit words):
//   A: 128 rows x 20 words (16 k + 4 pad) = 2560 words (bank-clean: 20m+k)
//   B: 16 rows, 16B-chunk XOR swizzle: phys_chunk = c ^ ((k&3)<<1)
// Stage = 4608 words = 18432 B; 4 stages = 73728 B dynamic smem.
// ---------------------------------------------------------------------------
#define STAGE_W 4608
#define STAGE_B 18432
#define SMEM_BYTES (4 * STAGE_B)

// ---------------------------------------------------------------------------
// Dual tf32 MMA GEMM (cp.async, 4-stage): act = silu(X@Wg)*(X@Wu) [* combine]
// Block 128x64, BK=16, 4 warps (2m x 2n), warp 64x32 dual.
// z<32: routed expert z. z>=32: shared N-slice (z-32)*512.
// ---------------------------------------------------------------------------
__global__ __launch_bounds__(128, 3)
void k_dual(const float* __restrict__ w_gate,
            const float* __restrict__ w_up,
            const float* __restrict__ ws_gate,
            const float* __restrict__ ws_up)
{
    extern __shared__ uint32_t sm[];
    const int z = blockIdx.z;
    const bool routed = z < E_NUM;
    const int e = routed ? z : 0;
    const int M = routed ? g_cnt[e] : T_TOK;
    const int m0 = blockIdx.y * 128;
    if (m0 >= M) return;
    const int NS = routed ? I_DIM : IS_DIM;
    const int n0 = routed ? blockIdx.x * 64
                          : (z - E_NUM) * 512 + blockIdx.x * 64;
    const float* __restrict__ Wg = routed ? w_gate + (size_t)e * H_DIM * I_DIM : ws_gate;
    const float* __restrict__ Wu = routed ? w_up   + (size_t)e * H_DIM * I_DIM : ws_up;
    uint32_t* __restrict__ Act = routed ? g_act + (size_t)e * T_TOK * I_DIM : g_sact;

    const uint32_t sb = smem_u32(sm);
    const int tid = threadIdx.x;
    const int warp = tid >> 5, lane = tid & 31;
    const int wm = warp & 1, wn = warp >> 1;
    const int grp = lane >> 2, tg = lane & 3;

    // cp.async A: 128 rows x 16k, 4 units/thread (16B each)
    const uint32_t* aSrc[4];
    uint32_t aDst[4], aSz[4];
    #pragma unroll
    for (int u = 0; u < 4; u++) {
        int idx = tid + u * 128;
        int am = idx >> 2, ak4 = idx & 3;
        int gm = m0 + am;
        bool ok = gm < M;
        int srow = ok ? (routed ? g_tok[e * T_TOK + gm] : gm) : 0;
        aSrc[u] = g_xtf + (size_t)srow * H_DIM + ak4 * 4;
        aDst[u] = (uint32_t)(am * 80 + ak4 * 16);
        aSz[u] = ok ? 16u : 0u;
    }
    // cp.async B: 16 rows x 64n per matrix, 2 units/thread/matrix
    const float* gSrc[2];
    const float* uSrc[2];
    uint32_t bDst[2];
    #pragma unroll
    for (int u = 0; u < 2; u++) {
        int idx = tid + u * 128;
        int bk = idx >> 4, bc = idx & 15;
        int cph = bc ^ ((bk & 3) << 1);
        gSrc[u] = Wg + (size_t)bk * NS + n0 + bc * 4;
        uSrc[u] = Wu + (size_t)bk * NS + n0 + bc * 4;
        bDst[u] = (uint32_t)(10240 + bk * 256 + cph * 16);
    }

    // fragment word offsets
    int aw[4];
    #pragma unroll
    for (int mi = 0; mi < 4; mi++)
        aw[mi] = (wm * 64 + mi * 16 + grp) * 20 + tg;
    int bw[4];
    #pragma unroll
    for (int ni = 0; ni < 4; ni++) {
        int n = wn * 32 + ni * 8 + grp;
        int cph = (n >> 2) ^ (tg << 1);
        bw[ni] = 2560 + tg * 64 + cph * 4 + (n & 3);
    }

    const int NC = H_DIM / 16;  // 64
    // prologue: stages 0..2
    #pragma unroll
    for (int c = 0; c < 3; c++) {
        uint32_t st = sb + c * STAGE_B;
        #pragma unroll
        for (int u = 0; u < 4; u++) CP16(st + aDst[u], aSrc[u] + c * 16, aSz[u]);
        #pragma unroll
        for (int u = 0; u < 2; u++) {
            CP16(st + bDst[u],        gSrc[u] + (size_t)c * 16 * NS, 16u);
            CP16(st + bDst[u] + 4096, uSrc[u] + (size_t)c * 16 * NS, 16u);
        }
        CP_COMMIT();
    }

    float cg[4][4][4], cu[4][4][4];
    #pragma unroll
    for (int mi = 0; mi < 4; mi++)
        #pragma unroll
        for (int ni = 0; ni < 4; ni++)
            #pragma unroll
            for (int q = 0; q < 4; q++) { cg[mi][ni][q] = 0.f; cu[mi][ni][q] = 0.f; }

    for (int c = 0; c < NC; c++) {
        CP_WAIT2();
        __syncthreads();
        // issue stage c+3 (its buffer was consumed in chunk c-1; sync above fences it)
        if (c + 3 < NC) {
            int c3 = c + 3;
            uint32_t st = sb + (c3 & 3) * STAGE_B;
            #pragma unroll
            for (int u = 0; u < 4; u++) CP16(st + aDst[u], aSrc[u] + c3 * 16, aSz[u]);
            #pragma unroll
            for (int u = 0; u < 2; u++) {
                CP16(st + bDst[u],        gSrc[u] + (size_t)c3 * 16 * NS, 16u);
                CP16(st + bDst[u] + 4096, uSrc[u] + (size_t)c3 * 16 * NS, 16u);
            }
        }
        CP_COMMIT();
        const uint32_t* S = sm + (c & 3) * STAGE_W;
        #pragma unroll
        for (int ks = 0; ks < 2; ks++) {
            const int kb = ks * 8;
            uint32_t af[4][4];
            #pragma unroll
            for (int mi = 0; mi < 4; mi++) {
                af[mi][0] = S[aw[mi] + kb];
                af[mi][1] = S[aw[mi] + 160 + kb];
                af[mi][2] = S[aw[mi] + kb + 4];
                af[mi][3] = S[aw[mi] + 160 + kb + 4];
            }
            #pragma unroll
            for (int ni = 0; ni < 4; ni++) {
                uint32_t bg0 = f2tf(__uint_as_float(S[bw[ni] + kb * 64]));
                uint32_t bg1 = f2tf(__uint_as_float(S[bw[ni] + (kb + 4) * 64]));
                uint32_t bu0 = f2tf(__uint_as_float(S[bw[ni] + 1024 + kb * 64]));
                uint32_t bu1 = f2tf(__uint_as_float(S[bw[ni] + 1024 + (kb + 4) * 64]));
                #pragma unroll
                for (int mi = 0; mi < 4; mi++) {
                    mma_tf32(cg[mi][ni], af[mi][0], af[mi][1], af[mi][2], af[mi][3], bg0, bg1);
                    mma_tf32(cu[mi][ni], af[mi][0], af[mi][1], af[mi][2], af[mi][3], bu0, bu1);
                }
            }
        }
    }

    // epilogue: silu(g)*u (* wgt), store tf32 bits
    #pragma unroll
    for (int mi = 0; mi < 4; mi++) {
        int r0 = m0 + wm * 64 + mi * 16 + grp;
        int r1 = r0 + 8;
        float w0 = 1.f, w1 = 1.f;
        if (routed) {
            if (r0 < M) w0 = g_wgt[e * T_TOK + r0];
            if (r1 < M) w1 = g_wgt[e * T_TOK + r1];
        }
        #pragma unroll
        for (int ni = 0; ni < 4; ni++) {
            int col = n0 + wn * 32 + ni * 8 + tg * 2;
            if (r0 < M) {
                uint2 v;
                v.x = f2tf(silu_f(cg[mi][ni][0]) * cu[mi][ni][0] * w0);
                v.y = f2tf(silu_f(cg[mi][ni][1]) * cu[mi][ni][1] * w0);
                *(uint2*)(Act + (size_t)r0 * NS + col) = v;
            }
            if (r1 < M) {
                uint2 v;
                v.x = f2tf(silu_f(cg[mi][ni][2]) * cu[mi][ni][2] * w1);
                v.y = f2tf(silu_f(cg[mi][ni][3]) * cu[mi][ni][3] * w1);
                *(uint2*)(Act + (size_t)r1 * NS + col) = v;
            }
        }
    }
}

// ---------------------------------------------------------------------------
// Down-proj tf32 MMA (cp.async, 4-stage): out += act @ Wd (atomicAdd)
// Block 128x128, BK=16, 4 warps (2m x 2n), warp 64x64.
// z<32: routed expert z. z>=32: shared K-slice (z-32)*512.
// ---------------------------------------------------------------------------
__global__ __launch_bounds__(128, 3)
void k_down(const float* __restrict__ w_down,
            const float* __restrict__ ws_down,
            float* __restrict__ Out)
{
    extern __shared__ uint32_t sm[];
    const int z = blockIdx.z;
    const bool routed = z < E_NUM;
    const int e = routed ? z : 0;
    const int M = routed ? g_cnt[e] : T_TOK;
    const int m0 = blockIdx.y * 128;
    if (m0 >= M) return;
    const int n0 = blockIdx.x * 128;
    const int koff = routed ? 0 : (z - E_NUM) * 512;
    const uint32_t* __restrict__ A = routed ? g_act + (size_t)e * T_TOK * I_DIM : g_sact;
    const int AS = routed ? I_DIM : IS_DIM;
    const float* __restrict__ B = routed ? w_down + (size_t)e * I_DIM * H_DIM
                                         : ws_down + (size_t)koff * H_DIM;
    const int N = H_DIM;

    const uint32_t sb = smem_u32(sm);
    const int tid = threadIdx.x;
    const int warp = tid >> 5, lane = tid & 31;
    const int wm = warp & 1, wn = warp >> 1;
    const int grp = lane >> 2, tg = lane & 3;

    // cp.async A: 128 rows x 16k, 4 units/thread
    const uint32_t* aSrc[4];
    uint32_t aDst[4], aSz[4];
    #pragma unroll
    for (int u = 0; u < 4; u++) {
        int idx = tid + u * 128;
        int am = idx >> 2, ak4 = idx & 3;
        int gm = m0 + am;
        bool ok = gm < M;
        aSrc[u] = A + (size_t)(ok ? gm : 0) * AS + koff + ak4 * 4;
        aDst[u] = (uint32_t)(am * 80 + ak4 * 16);
        aSz[u] = ok ? 16u : 0u;
    }
    // cp.async B: 16 rows x 128n, 4 units/thread
    const float* bSrc[4];
    uint32_t bDst[4];
    #pragma unroll
    for (int u = 0; u < 4; u++) {
        int idx = tid + u * 128;
        int bk = idx >> 5, bc = idx & 31;
        int cph = bc ^ ((bk & 3) << 1);
        bSrc[u] = B + (size_t)bk * N + n0 + bc * 4;
        bDst[u] = (uint32_t)(10240 + bk * 512 + cph * 16);
    }

    int aw[4];
    #pragma unroll
    for (int mi = 0; mi < 4; mi++)
        aw[mi] = (wm * 64 + mi * 16 + grp) * 20 + tg;
    int bw[8];
    #pragma unroll
    for (int ni = 0; ni < 8; ni++) {
        int n = wn * 64 + ni * 8 + grp;
        int cph = (n >> 2) ^ (tg << 1);
        bw[ni] = 2560 + tg * 128 + cph * 4 + (n & 3);
    }

    const int NC = 512 / 16;  // 32
    #pragma unroll
    for (int c = 0; c < 3; c++) {
        uint32_t st = sb + c * STAGE_B;
        #pragma unroll
        for (int u = 0; u < 4; u++) {
            CP16(st + aDst[u], aSrc[u] + c * 16, aSz[u]);
            CP16(st + bDst[u], bSrc[u] + (size_t)c * 16 * N, 16u);
        }
        CP_COMMIT();
    }

    float acc[4][8][4];
    #pragma unroll
    for (int mi = 0; mi < 4; mi++)
        #pragma unroll
        for (int ni = 0; ni < 8; ni++)
            #pragma unroll
            for (int q = 0; q < 4; q++) acc[mi][ni][q] = 0.f;

    for (int c = 0; c < NC; c++) {
        CP_WAIT2();
        __syncthreads();
        if (c + 3 < NC) {
            int c3 = c + 3;
            uint32_t st = sb + (c3 & 3) * STAGE_B;
            #pragma unroll
            for (int u = 0; u < 4; u++) {
                CP16(st + aDst[u], aSrc[u] + c3 * 16, aSz[u]);
                CP16(st + bDst[u], bSrc[u] + (size_t)c3 * 16 * N, 16u);
            }
        }
        CP_COMMIT();
        const uint32_t* S = sm + (c & 3) * STAGE_W;
        #pragma unroll
        for (int ks = 0; ks < 2; ks++) {
            const int kb = ks * 8;
            uint32_t af[4][4];
            #pragma unroll
            for (int mi = 0; mi < 4; mi++) {
                af[mi][0] = S[aw[mi] + kb];
                af[mi][1] = S[aw[mi] + 160 + kb];
                af[mi][2] = S[aw[mi] + kb + 4];
                af[mi][3] = S[aw[mi] + 160 + kb + 4];
            }
            #pragma unroll
            for (int ni = 0; ni < 8; ni++) {
                uint32_t b0 = f2tf(__uint_as_float(S[bw[ni] + kb * 128]));
                uint32_t b1 = f2tf(__uint_as_float(S[bw[ni] + (kb + 4) * 128]));
                #pragma unroll
                for (int mi = 0; mi < 4; mi++)
                    mma_tf32(acc[mi][ni], af[mi][0], af[mi][1], af[mi][2], af[mi][3], b0, b1);
            }
        }
    }

    #pragma unroll
    for (int mi = 0; mi < 4; mi++) {
        int r0 = m0 + wm * 64 + mi * 16 + grp;
        int r1 = r0 + 8;
        int tok0 = 0, tok1 = 0;
        bool ok0 = r0 < M, ok1 = r1 < M;
        if (routed) {
            if (ok0) tok0 = g_tok[e * T_TOK + r0];
            if (ok1) tok1 = g_tok[e * T_TOK + r1];
        } else { tok0 = r0; tok1 = r1; }
        #pragma unroll
        for (int ni = 0; ni < 8; ni++) {
            int col = n0 + wn * 64 + ni * 8 + tg * 2;
            if (ok0) {
                atomicAdd(Out + (size_t)tok0 * N + col,     acc[mi][ni][0]);
                atomicAdd(Out + (size_t)tok0 * N + col + 1, acc[mi][ni][1]);
            }
            if (ok1) {
                atomicAdd(Out + (size_t)tok1 * N + col,     acc[mi][ni][2]);
                atomicAdd(Out + (size_t)tok1 * N + col + 1, acc[mi][ni][3]);
            }
        }
    }
}

// ---------------------------------------------------------------------------
extern "C" void kernel_launch(void* const* d_in, const int* in_sizes, int n_in,
                              void* d_out, int out_size)
{
    const float* x       = (const float*)d_in[0];
    const float* gate_w  = (const float*)d_in[1];
    const float* e_bias  = (const float*)d_in[2];
    const float* w_gate  = (const float*)d_in[3];
    const float* w_up    = (const float*)d_in[4];
    const float* w_down  = (const float*)d_in[5];
    const float* ws_gate = (const float*)d_in[6];
    const float* ws_up   = (const float*)d_in[7];
    const float* ws_down = (const float*)d_in[8];
    float* out = (float*)d_out;

    static bool attr_done = false;
    if (!attr_done) {
        cudaFuncSetAttribute(k_dual, cudaFuncAttributeMaxDynamicSharedMemorySize, SMEM_BYTES);
        cudaFuncSetAttribute(k_down, cudaFuncAttributeMaxDynamicSharedMemorySize, SMEM_BYTES);
        attr_done = true;
    }

    k_init<<<(T_TOK * H_DIM) / (256 * 4), 256>>>(out);
    k_xtf<<<(T_TOK * H_DIM) / (256 * 4), 256>>>(x);
    k_gate_route<<<T_TOK, 256>>>(x, gate_w, e_bias);
    // dual GEMMs: routed z=0..31, shared z=32..35
    k_dual<<<dim3(8, 8, E_NUM + 4), 128, SMEM_BYTES>>>(w_gate, w_up, ws_gate, ws_up);
    // down GEMMs: routed z=0..31, shared split-K z=32..35
    k_down<<<dim3(8, 8, E_NUM + 4), 128, SMEM_BYTES>>>(w_down, ws_down, out);
}

// round 8
// speedup vs baseline: 1.1975x; 1.1975x over previous
#include <cuda_runtime.h>
#include <math.h>
#include <stdint.h>

#define T_TOK 1024
#define H_DIM 1024
#define E_NUM 32
#define I_DIM 512
#define IS_DIM 2048
#define NGROUP 8
#define GSIZE 4
#define TOPKG 4
#define TOPK 8
#define RSCALE 2.5f

// Scratch: activations stored as tf32 bit patterns (pre-converted)
__device__ uint32_t g_xtf[(size_t)T_TOK * H_DIM];
__device__ uint32_t g_act[(size_t)E_NUM * T_TOK * I_DIM];
__device__ uint32_t g_sact[(size_t)T_TOK * IS_DIM];
__device__ float g_dact[(size_t)E_NUM * T_TOK * H_DIM];   // routed down staging
__device__ float g_sds[4][(size_t)T_TOK * H_DIM];         // shared split-K staging
__device__ int   g_cnt[E_NUM];
__device__ int   g_tok[E_NUM * T_TOK];
__device__ float g_wgt[E_NUM * T_TOK];
__device__ int   g_pos[T_TOK * TOPK];                     // token -> 8 (e*T+slot)

__device__ __forceinline__ float silu_f(float v) { return v / (1.f + expf(-v)); }

__device__ __forceinline__ uint32_t f2tf(float f) {
    uint32_t u;
    asm("cvt.rna.tf32.f32 %0, %1;" : "=r"(u) : "f"(f));
    return u;
}

__device__ __forceinline__ uint32_t smem_u32(const void* p) {
    uint32_t a;
    asm("{ .reg .u64 t; cvta.to.shared.u64 t, %1; cvt.u32.u64 %0, t; }" : "=r"(a) : "l"(p));
    return a;
}

__device__ __forceinline__ void mma_tf32(float* c,
                                         uint32_t a0, uint32_t a1, uint32_t a2, uint32_t a3,
                                         uint32_t b0, uint32_t b1)
{
    asm volatile(
        "mma.sync.aligned.m16n8k8.row.col.f32.tf32.tf32.f32 "
        "{%0,%1,%2,%3}, {%4,%5,%6,%7}, {%8,%9}, {%0,%1,%2,%3};\n"
        : "+f"(c[0]), "+f"(c[1]), "+f"(c[2]), "+f"(c[3])
        : "r"(a0), "r"(a1), "r"(a2), "r"(a3), "r"(b0), "r"(b1));
}

#define CP16(dst, src, sz) \
    asm volatile("cp.async.cg.shared.global [%0], [%1], 16, %2;" \
                 :: "r"(dst), "l"(src), "r"(sz) : "memory")
#define CP_COMMIT() asm volatile("cp.async.commit_group;" ::: "memory")
#define CP_WAIT1()  asm volatile("cp.async.wait_group 1;" ::: "memory")

// convert X -> tf32 bits once; block 0 zeroes expert counters
__global__ void k_xtf(const float* __restrict__ x) {
    if (blockIdx.x == 0 && threadIdx.x < E_NUM) g_cnt[threadIdx.x] = 0;
    size_t i = (size_t)blockIdx.x * 256 + threadIdx.x;
    float4 v = ((const float4*)x)[i];
    ((uint4*)g_xtf)[i] = make_uint4(f2tf(v.x), f2tf(v.y), f2tf(v.z), f2tf(v.w));
}

// ---------------------------------------------------------------------------
// Gate GEMV + DeepseekV3 noaux_tc routing + per-expert gather
// ---------------------------------------------------------------------------
__global__ __launch_bounds__(256) void k_gate_route(
    const float* __restrict__ x,
    const float* __restrict__ gate_w,
    const float* __restrict__ e_bias)
{
    __shared__ float s_logit[E_NUM];
    const int t = blockIdx.x;
    const int warp = threadIdx.x >> 5, lane = threadIdx.x & 31;
    const float* xr = x + (size_t)t * H_DIM;
    for (int e = warp; e < E_NUM; e += 8) {
        const float* gw = gate_w + (size_t)e * H_DIM;
        float s = 0.f;
        for (int k = lane; k < H_DIM; k += 32) s += xr[k] * gw[k];
        #pragma unroll
        for (int o = 16; o; o >>= 1) s += __shfl_xor_sync(0xffffffffu, s, o);
        if (lane == 0) s_logit[e] = s;
    }
    __syncthreads();
    if (threadIdx.x != 0) return;

    float scores[E_NUM], swb[E_NUM];
    for (int e = 0; e < E_NUM; e++) {
        float sc = 1.f / (1.f + expf(-s_logit[e]));
        scores[e] = sc;
        swb[e] = sc + e_bias[e];
    }
    float gs[NGROUP];
    for (int g = 0; g < NGROUP; g++) {
        float m1 = -1e30f, m2 = -1e30f;
        for (int j = 0; j < GSIZE; j++) {
            float v = swb[g * GSIZE + j];
            if (v > m1) { m2 = m1; m1 = v; }
            else if (v > m2) m2 = v;
        }
        gs[g] = m1 + m2;
    }
    bool gsel[NGROUP] = {false};
    for (int it = 0; it < TOPKG; it++) {
        int bi = 0; float bv = -1e30f;
        for (int g = 0; g < NGROUP; g++)
            if (!gsel[g] && gs[g] > bv) { bv = gs[g]; bi = g; }
        gsel[bi] = true;
    }
    float val[E_NUM];
    for (int e = 0; e < E_NUM; e++) val[e] = gsel[e / GSIZE] ? swb[e] : 0.f;
    bool taken[E_NUM] = {false};
    int sel[TOPK];
    float denom = 0.f;
    for (int it = 0; it < TOPK; it++) {
        int bi = 0; float bv = -1e30f;
        for (int e = 0; e < E_NUM; e++)
            if (!taken[e] && val[e] > bv) { bv = val[e]; bi = e; }
        taken[bi] = true; sel[it] = bi; denom += scores[bi];
    }
    float inv = RSCALE / (denom + 1e-20f);
    for (int it = 0; it < TOPK; it++) {
        int e = sel[it];
        int slot = atomicAdd(&g_cnt[e], 1);
        g_tok[e * T_TOK + slot] = t;
        g_wgt[e * T_TOK + slot] = scores[e] * inv;
        g_pos[t * TOPK + it] = e * T_TOK + slot;
    }
}

// ---------------------------------------------------------------------------
// Shared layout per stage (32-bit words):
//   A: 128 rows x 20 words (16 k + 4 pad) = 2560 words (bank-clean: 20m+k)
//   B: 16 rows, 16B-chunk XOR swizzle: phys_chunk = c ^ ((k&3)<<1)
// Stage = 4608 words = 18432 B; 3 stages = 55296 B dynamic smem.
// ---------------------------------------------------------------------------
#define STAGE_W 4608
#define STAGE_B 18432
#define SMEM_BYTES (3 * STAGE_B)

// ---------------------------------------------------------------------------
// Dual tf32 MMA GEMM (cp.async, 3-stage): act = silu(X@Wg)*(X@Wu) [* combine]
// Block 128x64, BK=16, 4 warps (2m x 2n), warp 64x32 dual.
// z<32: routed expert z. z>=32: shared N-slice (z-32)*512.
// ---------------------------------------------------------------------------
__global__ __launch_bounds__(128, 3)
void k_dual(const float* __restrict__ w_gate,
            const float* __restrict__ w_up,
            const float* __restrict__ ws_gate,
            const float* __restrict__ ws_up)
{
    extern __shared__ uint32_t sm[];
    const int z = blockIdx.z;
    const bool routed = z < E_NUM;
    const int e = routed ? z : 0;
    const int M = routed ? g_cnt[e] : T_TOK;
    const int m0 = blockIdx.y * 128;
    if (m0 >= M) return;
    const int NS = routed ? I_DIM : IS_DIM;
    const int n0 = routed ? blockIdx.x * 64
                          : (z - E_NUM) * 512 + blockIdx.x * 64;
    const float* __restrict__ Wg = routed ? w_gate + (size_t)e * H_DIM * I_DIM : ws_gate;
    const float* __restrict__ Wu = routed ? w_up   + (size_t)e * H_DIM * I_DIM : ws_up;
    uint32_t* __restrict__ Act = routed ? g_act + (size_t)e * T_TOK * I_DIM : g_sact;

    const uint32_t sb = smem_u32(sm);
    const int tid = threadIdx.x;
    const int warp = tid >> 5, lane = tid & 31;
    const int wm = warp & 1, wn = warp >> 1;
    const int grp = lane >> 2, tg = lane & 3;

    // cp.async A: 128 rows x 16k, 4 units/thread (16B each)
    const uint32_t* aSrc[4];
    uint32_t aDst[4], aSz[4];
    #pragma unroll
    for (int u = 0; u < 4; u++) {
        int idx = tid + u * 128;
        int am = idx >> 2, ak4 = idx & 3;
        int gm = m0 + am;
        bool ok = gm < M;
        int srow = ok ? (routed ? g_tok[e * T_TOK + gm] : gm) : 0;
        aSrc[u] = g_xtf + (size_t)srow * H_DIM + ak4 * 4;
        aDst[u] = (uint32_t)(am * 80 + ak4 * 16);
        aSz[u] = ok ? 16u : 0u;
    }
    // cp.async B: 16 rows x 64n per matrix, 2 units/thread/matrix
    const float* gSrc[2];
    const float* uSrc[2];
    uint32_t bDst[2];
    #pragma unroll
    for (int u = 0; u < 2; u++) {
        int idx = tid + u * 128;
        int bk = idx >> 4, bc = idx & 15;
        int cph = bc ^ ((bk & 3) << 1);
        gSrc[u] = Wg + (size_t)bk * NS + n0 + bc * 4;
        uSrc[u] = Wu + (size_t)bk * NS + n0 + bc * 4;
        bDst[u] = (uint32_t)(10240 + bk * 256 + cph * 16);
    }

    // fragment word offsets
    int aw[4];
    #pragma unroll
    for (int mi = 0; mi < 4; mi++)
        aw[mi] = (wm * 64 + mi * 16 + grp) * 20 + tg;
    int bw[4];
    #pragma unroll
    for (int ni = 0; ni < 4; ni++) {
        int n = wn * 32 + ni * 8 + grp;
        int cph = (n >> 2) ^ (tg << 1);
        bw[ni] = 2560 + tg * 64 + cph * 4 + (n & 3);
    }

    const int NC = H_DIM / 16;  // 64
    // prologue: stages 0, 1
    #pragma unroll
    for (int c = 0; c < 2; c++) {
        uint32_t st = sb + c * STAGE_B;
        #pragma unroll
        for (int u = 0; u < 4; u++) CP16(st + aDst[u], aSrc[u] + c * 16, aSz[u]);
        #pragma unroll
        for (int u = 0; u < 2; u++) {
            CP16(st + bDst[u],        gSrc[u] + (size_t)c * 16 * NS, 16u);
            CP16(st + bDst[u] + 4096, uSrc[u] + (size_t)c * 16 * NS, 16u);
        }
        CP_COMMIT();
    }

    float cg[4][4][4], cu[4][4][4];
    #pragma unroll
    for (int mi = 0; mi < 4; mi++)
        #pragma unroll
        for (int ni = 0; ni < 4; ni++)
            #pragma unroll
            for (int q = 0; q < 4; q++) { cg[mi][ni][q] = 0.f; cu[mi][ni][q] = 0.f; }

    for (int c = 0; c < NC; c++) {
        CP_WAIT1();
        __syncthreads();
        if (c + 2 < NC) {
            int c2 = c + 2;
            uint32_t st = sb + (c2 % 3) * STAGE_B;
            #pragma unroll
            for (int u = 0; u < 4; u++) CP16(st + aDst[u], aSrc[u] + c2 * 16, aSz[u]);
            #pragma unroll
            for (int u = 0; u < 2; u++) {
                CP16(st + bDst[u],        gSrc[u] + (size_t)c2 * 16 * NS, 16u);
                CP16(st + bDst[u] + 4096, uSrc[u] + (size_t)c2 * 16 * NS, 16u);
            }
        }
        CP_COMMIT();
        const uint32_t* S = sm + (c % 3) * STAGE_W;
        #pragma unroll
        for (int ks = 0; ks < 2; ks++) {
            const int kb = ks * 8;
            uint32_t af[4][4];
            #pragma unroll
            for (int mi = 0; mi < 4; mi++) {
                af[mi][0] = S[aw[mi] + kb];
                af[mi][1] = S[aw[mi] + 160 + kb];
                af[mi][2] = S[aw[mi] + kb + 4];
                af[mi][3] = S[aw[mi] + 160 + kb + 4];
            }
            #pragma unroll
            for (int ni = 0; ni < 4; ni++) {
                uint32_t bg0 = f2tf(__uint_as_float(S[bw[ni] + kb * 64]));
                uint32_t bg1 = f2tf(__uint_as_float(S[bw[ni] + (kb + 4) * 64]));
                uint32_t bu0 = f2tf(__uint_as_float(S[bw[ni] + 1024 + kb * 64]));
                uint32_t bu1 = f2tf(__uint_as_float(S[bw[ni] + 1024 + (kb + 4) * 64]));
                #pragma unroll
                for (int mi = 0; mi < 4; mi++) {
                    mma_tf32(cg[mi][ni], af[mi][0], af[mi][1], af[mi][2], af[mi][3], bg0, bg1);
                    mma_tf32(cu[mi][ni], af[mi][0], af[mi][1], af[mi][2], af[mi][3], bu0, bu1);
                }
            }
        }
    }

    // epilogue: silu(g)*u (* wgt), store tf32 bits
    #pragma unroll
    for (int mi = 0; mi < 4; mi++) {
        int r0 = m0 + wm * 64 + mi * 16 + grp;
        int r1 = r0 + 8;
        float w0 = 1.f, w1 = 1.f;
        if (routed) {
            if (r0 < M) w0 = g_wgt[e * T_TOK + r0];
            if (r1 < M) w1 = g_wgt[e * T_TOK + r1];
        }
        #pragma unroll
        for (int ni = 0; ni < 4; ni++) {
            int col = n0 + wn * 32 + ni * 8 + tg * 2;
            if (r0 < M) {
                uint2 v;
                v.x = f2tf(silu_f(cg[mi][ni][0]) * cu[mi][ni][0] * w0);
                v.y = f2tf(silu_f(cg[mi][ni][1]) * cu[mi][ni][1] * w0);
                *(uint2*)(Act + (size_t)r0 * NS + col) = v;
            }
            if (r1 < M) {
                uint2 v;
                v.x = f2tf(silu_f(cg[mi][ni][2]) * cu[mi][ni][2] * w1);
                v.y = f2tf(silu_f(cg[mi][ni][3]) * cu[mi][ni][3] * w1);
                *(uint2*)(Act + (size_t)r1 * NS + col) = v;
            }
        }
    }
}

// ---------------------------------------------------------------------------
// Down-proj tf32 MMA (cp.async, 3-stage): plain stores to staging
// z<32: routed expert z -> g_dact[e][slot][:]. z>=32: shared K-slice -> g_sds.
// Block 128x128, BK=16, 4 warps (2m x 2n), warp 64x64.
// ---------------------------------------------------------------------------
__global__ __launch_bounds__(128, 3)
void k_down(const float* __restrict__ w_down,
            const float* __restrict__ ws_down)
{
    extern __shared__ uint32_t sm[];
    const int z = blockIdx.z;
    const bool routed = z < E_NUM;
    const int e = routed ? z : 0;
    const int M = routed ? g_cnt[e] : T_TOK;
    const int m0 = blockIdx.y * 128;
    if (m0 >= M) return;
    const int n0 = blockIdx.x * 128;
    const int koff = routed ? 0 : (z - E_NUM) * 512;
    const uint32_t* __restrict__ A = routed ? g_act + (size_t)e * T_TOK * I_DIM : g_sact;
    const int AS = routed ? I_DIM : IS_DIM;
    const float* __restrict__ B = routed ? w_down + (size_t)e * I_DIM * H_DIM
                                         : ws_down + (size_t)koff * H_DIM;
    float* __restrict__ Dst = routed ? g_dact + (size_t)e * T_TOK * H_DIM
                                     : g_sds[z - E_NUM];
    const int N = H_DIM;

    const uint32_t sb = smem_u32(sm);
    const int tid = threadIdx.x;
    const int warp = tid >> 5, lane = tid & 31;
    const int wm = warp & 1, wn = warp >> 1;
    const int grp = lane >> 2, tg = lane & 3;

    // cp.async A: 128 rows x 16k, 4 units/thread
    const uint32_t* aSrc[4];
    uint32_t aDst[4], aSz[4];
    #pragma unroll
    for (int u = 0; u < 4; u++) {
        int idx = tid + u * 128;
        int am = idx >> 2, ak4 = idx & 3;
        int gm = m0 + am;
        bool ok = gm < M;
        aSrc[u] = A + (size_t)(ok ? gm : 0) * AS + koff + ak4 * 4;
        aDst[u] = (uint32_t)(am * 80 + ak4 * 16);
        aSz[u] = ok ? 16u : 0u;
    }
    // cp.async B: 16 rows x 128n, 4 units/thread
    const float* bSrc[4];
    uint32_t bDst[4];
    #pragma unroll
    for (int u = 0; u < 4; u++) {
        int idx = tid + u * 128;
        int bk = idx >> 5, bc = idx & 31;
        int cph = bc ^ ((bk & 3) << 1);
        bSrc[u] = B + (size_t)bk * N + n0 + bc * 4;
        bDst[u] = (uint32_t)(10240 + bk * 512 + cph * 16);
    }

    int aw[4];
    #pragma unroll
    for (int mi = 0; mi < 4; mi++)
        aw[mi] = (wm * 64 + mi * 16 + grp) * 20 + tg;
    int bw[8];
    #pragma unroll
    for (int ni = 0; ni < 8; ni++) {
        int n = wn * 64 + ni * 8 + grp;
        int cph = (n >> 2) ^ (tg << 1);
        bw[ni] = 2560 + tg * 128 + cph * 4 + (n & 3);
    }

    const int NC = 512 / 16;  // 32
    #pragma unroll
    for (int c = 0; c < 2; c++) {
        uint32_t st = sb + c * STAGE_B;
        #pragma unroll
        for (int u = 0; u < 4; u++) {
            CP16(st + aDst[u], aSrc[u] + c * 16, aSz[u]);
            CP16(st + bDst[u], bSrc[u] + (size_t)c * 16 * N, 16u);
        }
        CP_COMMIT();
    }

    float acc[4][8][4];
    #pragma unroll
    for (int mi = 0; mi < 4; mi++)
        #pragma unroll
        for (int ni = 0; ni < 8; ni++)
            #pragma unroll
            for (int q = 0; q < 4; q++) acc[mi][ni][q] = 0.f;

    for (int c = 0; c < NC; c++) {
        CP_WAIT1();
        __syncthreads();
        if (c + 2 < NC) {
            int c2 = c + 2;
            uint32_t st = sb + (c2 % 3) * STAGE_B;
            #pragma unroll
            for (int u = 0; u < 4; u++) {
                CP16(st + aDst[u], aSrc[u] + c2 * 16, aSz[u]);
                CP16(st + bDst[u], bSrc[u] + (size_t)c2 * 16 * N, 16u);
            }
        }
        CP_COMMIT();
        const uint32_t* S = sm + (c % 3) * STAGE_W;
        #pragma unroll
        for (int ks = 0; ks < 2; ks++) {
            const int kb = ks * 8;
            uint32_t af[4][4];
            #pragma unroll
            for (int mi = 0; mi < 4; mi++) {
                af[mi][0] = S[aw[mi] + kb];
                af[mi][1] = S[aw[mi] + 160 + kb];
                af[mi][2] = S[aw[mi] + kb + 4];
                af[mi][3] = S[aw[mi] + 160 + kb + 4];
            }
            #pragma unroll
            for (int ni = 0; ni < 8; ni++) {
                uint32_t b0 = f2tf(__uint_as_float(S[bw[ni] + kb * 128]));
                uint32_t b1 = f2tf(__uint_as_float(S[bw[ni] + (kb + 4) * 128]));
                #pragma unroll
                for (int mi = 0; mi < 4; mi++)
                    mma_tf32(acc[mi][ni], af[mi][0], af[mi][1], af[mi][2], af[mi][3], b0, b1);
            }
        }
    }

    // epilogue: plain stores to staging (no atomics)
    #pragma unroll
    for (int mi = 0; mi < 4; mi++) {
        int r0 = m0 + wm * 64 + mi * 16 + grp;
        int r1 = r0 + 8;
        bool ok0 = r0 < M, ok1 = r1 < M;
        #pragma unroll
        for (int ni = 0; ni < 8; ni++) {
            int col = n0 + wn * 64 + ni * 8 + tg * 2;
            if (ok0) {
                float2 v = make_float2(acc[mi][ni][0], acc[mi][ni][1]);
                *(float2*)(Dst + (size_t)r0 * N + col) = v;
            }
            if (ok1) {
                float2 v = make_float2(acc[mi][ni][2], acc[mi][ni][3]);
                *(float2*)(Dst + (size_t)r1 * N + col) = v;
            }
        }
    }
}

// ---------------------------------------------------------------------------
// Final gather-reduce: out[t] = sum_{i<8} g_dact[pos_i] + sum_{s<4} g_sds[s][t]
// one block per token, 256 threads, each one float4 (h = tid*4)
// ---------------------------------------------------------------------------
__global__ __launch_bounds__(256) void k_reduce(float* __restrict__ out) {
    __shared__ int pos[TOPK];
    const int t = blockIdx.x;
    if (threadIdx.x < TOPK) pos[threadIdx.x] = g_pos[t * TOPK + threadIdx.x];
    __syncthreads();
    const int h = threadIdx.x * 4;
    float4 s = *(const float4*)(&g_sds[0][(size_t)t * H_DIM + h]);
    #pragma unroll
    for (int q = 1; q < 4; q++) {
        float4 v = *(const float4*)(&g_sds[q][(size_t)t * H_DIM + h]);
        s.x += v.x; s.y += v.y; s.z += v.z; s.w += v.w;
    }
    #pragma unroll
    for (int i = 0; i < TOPK; i++) {
        float4 v = *(const float4*)(g_dact + (size_t)pos[i] * H_DIM + h);
        s.x += v.x; s.y += v.y; s.z += v.z; s.w += v.w;
    }
    *(float4*)(out + (size_t)t * H_DIM + h) = s;
}

// ---------------------------------------------------------------------------
extern "C" void kernel_launch(void* const* d_in, const int* in_sizes, int n_in,
                              void* d_out, int out_size)
{
    const float* x       = (const float*)d_in[0];
    const float* gate_w  = (const float*)d_in[1];
    const float* e_bias  = (const float*)d_in[2];
    const float* w_gate  = (const float*)d_in[3];
    const float* w_up    = (const float*)d_in[4];
    const float* w_down  = (const float*)d_in[5];
    const float* ws_gate = (const float*)d_in[6];
    const float* ws_up   = (const float*)d_in[7];
    const float* ws_down = (const float*)d_in[8];
    float* out = (float*)d_out;

    static bool attr_done = false;
    if (!attr_done) {
        cudaFuncSetAttribute(k_dual, cudaFuncAttributeMaxDynamicSharedMemorySize, SMEM_BYTES);
        cudaFuncSetAttribute(k_down, cudaFuncAttributeMaxDynamicSharedMemorySize, SMEM_BYTES);
        attr_done = true;
    }

    k_xtf<<<(T_TOK * H_DIM) / (256 * 4), 256>>>(x);
    k_gate_route<<<T_TOK, 256>>>(x, gate_w, e_bias);
    // dual GEMMs: routed z=0..31, shared z=32..35
    k_dual<<<dim3(8, 8, E_NUM + 4), 128, SMEM_BYTES>>>(w_gate, w_up, ws_gate, ws_up);
    // down GEMMs (staged, no atomics): routed z=0..31, shared split-K z=32..35
    k_down<<<dim3(8, 8, E_NUM + 4), 128, SMEM_BYTES>>>(w_down, ws_down);
    // final combine
    k_reduce<<<T_TOK, 256>>>(out);
}